// round 12
// baseline (speedup 1.0000x reference)
#include <cuda_runtime.h>

#define N_ENT  100000
#define EMB    64
#define NREL   32
#define NEDGE  1000000
#define WARPS  8
#define EPA    8    // edges per warp-batch in attA (NEDGE % EPA == 0 -> always full)
#define EPB    4    // edges per batch in passB
#define SCAN_BLKS ((N_ENT + 1023) / 1024)   // 98

typedef unsigned long long ull;

// ---------------- static device scratch (no allocation allowed) ----------------
__device__ float g_Q[N_ENT * EMB];       // (agg @ q_w)
__device__ float g_agg[N_ENT * EMB];     // agg after hop 1
__device__ float g_att[NEDGE];           // attention logits (CSR order)
__device__ int   g_deg[N_ENT];
__device__ int   g_rowptr[N_ENT + 1];
__device__ int   g_cursor[N_ENT];
__device__ int   g_bsum[128];            // scan block sums
__device__ int   g_packc[NEDGE];         // CSR-ordered (tail | type<<17)
__device__ int   g_headc[NEDGE];         // CSR-ordered head

// ---------------- PTX helpers (sm_100+) ----------------
__device__ __forceinline__ ull fma2(ull a, ull b, ull c) {
    ull d;
    asm("fma.rn.f32x2 %0, %1, %2, %3;" : "=l"(d) : "l"(a), "l"(b), "l"(c));
    return d;
}
__device__ __forceinline__ float2 up2(ull v) {
    float2 f;
    asm("mov.b64 {%0, %1}, %2;" : "=f"(f.x), "=f"(f.y) : "l"(v));
    return f;
}
__device__ __forceinline__ float tanha(float x) {
    float y;
    asm("tanh.approx.f32 %0, %1;" : "=f"(y) : "f"(x));
    return y;
}
__device__ __forceinline__ float neg_inf() { return __int_as_float(0xff800000U); }

// ---------------- CSR build ----------------
__global__ void zero_deg_kernel() {
    int i = blockIdx.x * blockDim.x + threadIdx.x;
    if (i < N_ENT) g_deg[i] = 0;
}

__global__ void count_kernel(const int* __restrict__ head) {
    int e = blockIdx.x * blockDim.x + threadIdx.x;
    if (e < NEDGE) atomicAdd(&g_deg[head[e]], 1);
}

__global__ void scan1_kernel() {
    __shared__ int sh[1024];
    int tid = threadIdx.x;
    int i = blockIdx.x * 1024 + tid;
    int v = (i < N_ENT) ? g_deg[i] : 0;
    sh[tid] = v;
    __syncthreads();
    for (int off = 1; off < 1024; off <<= 1) {
        int t = (tid >= off) ? sh[tid - off] : 0;
        __syncthreads();
        sh[tid] += t;
        __syncthreads();
    }
    if (i < N_ENT) g_rowptr[i] = sh[tid] - v;
    if (tid == 1023) g_bsum[blockIdx.x] = sh[1023];
}

__global__ void scan2_kernel() {
    __shared__ int sh[128];
    int tid = threadIdx.x;
    int v = (tid < SCAN_BLKS) ? g_bsum[tid] : 0;
    sh[tid] = v;
    __syncthreads();
    for (int off = 1; off < 128; off <<= 1) {
        int t = (tid >= off) ? sh[tid - off] : 0;
        __syncthreads();
        sh[tid] += t;
        __syncthreads();
    }
    g_bsum[tid] = sh[tid] - v;
}

__global__ void scan3_kernel() {
    int i = blockIdx.x * blockDim.x + threadIdx.x;
    if (i < N_ENT) {
        int r = g_rowptr[i] + g_bsum[i >> 10];
        g_rowptr[i] = r;
        g_cursor[i] = r;
    }
    if (i == 0) g_rowptr[N_ENT] = NEDGE;
}

__global__ void fill_kernel(const int* __restrict__ head,
                            const int* __restrict__ tail,
                            const int* __restrict__ etype) {
    int e = blockIdx.x * blockDim.x + threadIdx.x;
    if (e < NEDGE) {
        int h = head[e];
        int pos = atomicAdd(&g_cursor[h], 1);
        g_packc[pos] = tail[e] | (etype[e] << 17);   // N_ENT < 2^17, NREL < 2^5
        g_headc[pos] = h;
    }
}

// ---------------- Q = agg @ q_w   (warp per row, packed f32x2 FMA) ----------------
__global__ void gemmq_kernel(const float* agg_in, const float* __restrict__ qw) {
    __shared__ ull qsm[EMB * 32];
    __shared__ ull xs[WARPS][EMB];
    const float* A = agg_in ? agg_in : g_agg;
    const ull* qw64 = (const ull*)qw;
    for (int idx = threadIdx.x; idx < EMB * 32; idx += blockDim.x) qsm[idx] = qw64[idx];
    __syncthreads();
    int w = threadIdx.x >> 5, l = threadIdx.x & 31;
    const float2* A2 = (const float2*)A;
    for (int row = blockIdx.x * WARPS + w; row < N_ENT; row += gridDim.x * WARPS) {
        float2 a2 = A2[row * 32 + l];
        ((float4*)xs[w])[l] = make_float4(a2.x, a2.x, a2.y, a2.y);
        __syncwarp();
        ull acc = 0ull;
        #pragma unroll 8
        for (int i = 0; i < EMB; i++) acc = fma2(qsm[i * 32 + l], xs[w][i], acc);
        float2 r = up2(acc);
        ((float2*)g_Q)[row * 32 + l] = r;
        __syncwarp();
    }
}

// ---------------- pass A: attention logits, edge-centric, software-pipelined --------
// Persistent grid (2 blocks/SM). Double-buffered register prefetch of packc/headc/
// A2[tail]; Q2[head] gathers issued just before the GEMM so they land during it.
// f32x2 lanes carry (even-k, odd-k) partials; xs undup'd so one broadcast LDS.128
// feeds 4 fma2; lane-major K tables give conflict-free kv LDS.128 shared by 8 edges.
__global__ void __launch_bounds__(256, 2) attA_kernel(const float* agg_in,
                                                      const float* __restrict__ edge_emb,
                                                      const float* __restrict__ kw) {
    __shared__ float4 ksmA[16 * 32];        // 8KB : [kb][l] = kw[4kb..4kb+3][2l]
    __shared__ float4 ksmB[16 * 32];        // 8KB : [kb][l] = kw[4kb..4kb+3][2l+1]
    __shared__ ull relsm[NREL * 32];        // 8KB
    __shared__ __align__(16) float xs[WARPS][EPA][EMB];  // 16KB (undup'd)
    const float* A = agg_in ? agg_in : g_agg;
    const ull* re64 = (const ull*)edge_emb;

    for (int idx = threadIdx.x; idx < 16 * 32; idx += blockDim.x) {
        int kb = idx >> 5, lc = idx & 31;
        int k0 = kb * 4;
        int d0 = lc * 2, d1 = lc * 2 + 1;
        ksmA[idx] = make_float4(kw[(k0 + 0) * EMB + d0], kw[(k0 + 1) * EMB + d0],
                                kw[(k0 + 2) * EMB + d0], kw[(k0 + 3) * EMB + d0]);
        ksmB[idx] = make_float4(kw[(k0 + 0) * EMB + d1], kw[(k0 + 1) * EMB + d1],
                                kw[(k0 + 2) * EMB + d1], kw[(k0 + 3) * EMB + d1]);
    }
    for (int idx = threadIdx.x; idx < NREL * 32; idx += blockDim.x) relsm[idx] = re64[idx];
    __syncthreads();

    int w = threadIdx.x >> 5, l = threadIdx.x & 31;
    const float2* A2 = (const float2*)A;
    const float2* Q2 = (const float2*)g_Q;

    const int stride = gridDim.x * WARPS * EPA;
    int base = (blockIdx.x * WARPS + w) * EPA;

    int pw[EPA], hh[EPA]; float2 ag[EPA];
    if (base < NEDGE) {                          // prefetch batch 0
        #pragma unroll
        for (int e = 0; e < EPA; e++) {
            pw[e] = g_packc[base + e];
            hh[e] = g_headc[base + e];
            ag[e] = A2[(pw[e] & 0x1FFFF) * 32 + l];
        }
    }

    while (base < NEDGE) {
        // consume prefetched: x = rel * agg[tail] -> xs (undup'd)
        #pragma unroll
        for (int e = 0; e < EPA; e++) {
            float2 rr = up2(relsm[(pw[e] >> 17) * 32 + l]);
            ((float2*)xs[w][e])[l] = make_float2(rr.x * ag[e].x, rr.y * ag[e].y);
        }

        // issue Q gathers for THIS batch (resolve during the GEMM)
        float2 qv[EPA];
        #pragma unroll
        for (int e = 0; e < EPA; e++) qv[e] = Q2[hh[e] * 32 + l];

        // prefetch NEXT batch (overwrites pw/hh/ag, all consumed above)
        int nb = base + stride;
        if (nb < NEDGE) {
            #pragma unroll
            for (int e = 0; e < EPA; e++) {
                pw[e] = g_packc[nb + e];
                hh[e] = g_headc[nb + e];
                ag[e] = A2[(pw[e] & 0x1FFFF) * 32 + l];
            }
        }
        __syncwarp();

        ull acc0[EPA], acc1[EPA];
        #pragma unroll
        for (int e = 0; e < EPA; e++) { acc0[e] = 0ull; acc1[e] = 0ull; }
        #pragma unroll
        for (int kb = 0; kb < 16; kb++) {
            ulonglong2 ka  = *(const ulonglong2*)&ksmA[kb * 32 + l];  // shared by 8 edges
            ulonglong2 kbv = *(const ulonglong2*)&ksmB[kb * 32 + l];
            #pragma unroll
            for (int e = 0; e < EPA; e++) {
                ulonglong2 xv = *(const ulonglong2*)&xs[w][e][kb * 4]; // broadcast, 4 k's
                acc0[e] = fma2(xv.x, ka.x,  acc0[e]);
                acc0[e] = fma2(xv.y, ka.y,  acc0[e]);
                acc1[e] = fma2(xv.x, kbv.x, acc1[e]);
                acc1[e] = fma2(xv.y, kbv.y, acc1[e]);
            }
        }

        #pragma unroll
        for (int e = 0; e < EPA; e++) {
            float2 s0 = up2(acc0[e]);   // (even-k, odd-k) partial sums for dim 2l
            float2 s1 = up2(acc1[e]);   // same for dim 2l+1
            float d = tanha(s0.x + s0.y) * qv[e].x + tanha(s1.x + s1.y) * qv[e].y;
            #pragma unroll
            for (int o = 16; o; o >>= 1) d += __shfl_xor_sync(0xffffffffu, d, o);
            if (l == e) g_att[base + e] = d;
        }
        __syncwarp();                   // GEMM reads done before next iter's xs stores
        base = nb;
    }
}

// ---------------- pass B: softmax + weighted scatter-mean + l2norm + kg ----------------
__global__ void passB_kernel(const float* agg_in,
                             const float* __restrict__ edge_emb,
                             const float* __restrict__ ent,
                             float* kg, int accumulate, int write_agg) {
    __shared__ ull relsm[NREL * 32];
    const float* A = agg_in ? agg_in : g_agg;
    const ull* re64 = (const ull*)edge_emb;
    for (int idx = threadIdx.x; idx < NREL * 32; idx += blockDim.x) relsm[idx] = re64[idx];
    __syncthreads();

    int w = threadIdx.x >> 5, l = threadIdx.x & 31;
    const float2* A2 = (const float2*)A;
    const float2* E2 = (const float2*)ent;
    float2* KG2 = (float2*)kg;

    for (int h = blockIdx.x * WARPS + w; h < N_ENT; h += gridDim.x * WARPS) {
        int rs = g_rowptr[h], re = g_rowptr[h + 1];
        int deg = re - rs;

        // sweep 1: exact max of logits (uniform broadcast loads, L1/L2 resident)
        float m = neg_inf();
        int j = rs;
        for (; j + 4 <= re; j += 4) {
            float v0 = g_att[j], v1 = g_att[j + 1], v2 = g_att[j + 2], v3 = g_att[j + 3];
            m = fmaxf(m, fmaxf(fmaxf(v0, v1), fmaxf(v2, v3)));
        }
        for (; j < re; j++) m = fmaxf(m, g_att[j]);

        // sweep 2: exp + gather + accumulate
        float ssum = 0.f, a0 = 0.f, a1 = 0.f;
        int pwv[EPB]; float avv[EPB]; float2 nag[EPB];
        int j0 = rs;
        if (j0 < re) {
            int nv = re - j0; if (nv > EPB) nv = EPB;
            #pragma unroll
            for (int e = 0; e < EPB; e++) {
                pwv[e] = (e < nv) ? g_packc[j0 + e] : 0;
                avv[e] = (e < nv) ? g_att[j0 + e] : neg_inf();
                nag[e] = (e < nv) ? A2[(pwv[e] & 0x1FFFF) * 32 + l] : make_float2(0.f, 0.f);
            }
        }
        while (j0 < re) {
            float x0[EPB], x1[EPB], p[EPB];
            #pragma unroll
            for (int e = 0; e < EPB; e++) {
                float2 rr = up2(relsm[(pwv[e] >> 17) * 32 + l]);
                x0[e] = rr.x * nag[e].x;
                x1[e] = rr.y * nag[e].y;
                p[e]  = __expf(avv[e] - m);          // -inf slots -> 0
            }
            int j1 = j0 + EPB;
            if (j1 < re) {                           // prefetch next batch
                int nv2 = re - j1; if (nv2 > EPB) nv2 = EPB;
                #pragma unroll
                for (int e = 0; e < EPB; e++) {
                    pwv[e] = (e < nv2) ? g_packc[j1 + e] : 0;
                    avv[e] = (e < nv2) ? g_att[j1 + e] : neg_inf();
                    nag[e] = (e < nv2) ? A2[(pwv[e] & 0x1FFFF) * 32 + l] : make_float2(0.f, 0.f);
                }
            }
            #pragma unroll
            for (int e = 0; e < EPB; e++) {
                ssum += p[e];
                a0   += p[e] * x0[e];
                a1   += p[e] * x1[e];
            }
            j0 = j1;
        }

        float v0 = 0.f, v1 = 0.f;
        if (deg > 0) {
            float inv = 1.f / (ssum * (float)deg);   // softmax denom * scatter_mean count
            v0 = a0 * inv; v1 = a1 * inv;
        }
        float sq = v0 * v0 + v1 * v1;
        #pragma unroll
        for (int o = 16; o; o >>= 1) sq += __shfl_xor_sync(0xffffffffu, sq, o);
        float rn = 1.f / fmaxf(sqrtf(sq), 1e-12f);
        v0 *= rn; v1 *= rn;

        if (write_agg) ((float2*)g_agg)[h * 32 + l] = make_float2(v0, v1);
        float2 e2 = E2[h * 32 + l];
        float2 o2;
        if (accumulate) {
            float2 kold = KG2[h * 32 + l];
            o2 = make_float2(kold.x + v0 + e2.x, kold.y + v1 + e2.y);
        } else {
            o2 = make_float2(v0 + e2.x, v1 + e2.y);
        }
        KG2[h * 32 + l] = o2;
    }
}

// ---------------- launch ----------------
extern "C" void kernel_launch(void* const* d_in, const int* in_sizes, int n_in,
                              void* d_out, int out_size) {
    const float* ent      = (const float*)d_in[0];
    const float* edge_emb = (const float*)d_in[1];
    const float* qw       = (const float*)d_in[2];
    const float* kw       = (const float*)d_in[3];
    const int*   eidx     = (const int*)d_in[4];
    const int*   etype    = (const int*)d_in[5];
    const int* head = eidx;
    const int* tail = eidx + NEDGE;
    float* kg = (float*)d_out;

    // CSR build (head identical across hops -> build once per launch)
    zero_deg_kernel<<<(N_ENT + 255) / 256, 256>>>();
    count_kernel<<<(NEDGE + 255) / 256, 256>>>(head);
    scan1_kernel<<<SCAN_BLKS, 1024>>>();
    scan2_kernel<<<1, 128>>>();
    scan3_kernel<<<(N_ENT + 255) / 256, 256>>>();
    fill_kernel<<<(NEDGE + 255) / 256, 256>>>(head, tail, etype);

    // hop 1: agg = entity_emb
    gemmq_kernel<<<2048, 256>>>(ent, qw);
    attA_kernel<<<296, 256>>>(ent, edge_emb, kw);        // persistent: 2 blocks/SM
    passB_kernel<<<3125, 256>>>(ent, edge_emb, ent, kg, /*accumulate=*/0, /*write_agg=*/1);

    // hop 2: agg = g_agg
    gemmq_kernel<<<2048, 256>>>(nullptr, qw);
    attA_kernel<<<296, 256>>>(nullptr, edge_emb, kw);
    passB_kernel<<<3125, 256>>>(nullptr, edge_emb, ent, kg, /*accumulate=*/1, /*write_agg=*/0);
}

// round 16
// speedup vs baseline: 1.5843x; 1.5843x over previous
#include <cuda_runtime.h>

#define N_ENT  100000
#define EMB    64
#define NREL   32
#define NEDGE  1000000
#define WARPS  8
#define EPA    8    // edges per warp-batch in attA (NEDGE % EPA == 0 -> always full)
#define EPB    4    // edges per batch in passB
#define SCAN_BLKS ((N_ENT + 1023) / 1024)   // 98

typedef unsigned long long ull;

// ---------------- static device scratch (no allocation allowed) ----------------
__device__ float g_Q[N_ENT * EMB];       // (agg @ q_w)
__device__ float g_agg[N_ENT * EMB];     // agg after hop 1
__device__ float g_att[NEDGE];           // attention logits (CSR order)
__device__ int   g_deg[N_ENT];
__device__ int   g_rowptr[N_ENT + 1];
__device__ int   g_cursor[N_ENT];
__device__ int   g_bsum[128];            // scan block sums
__device__ int   g_packc[NEDGE];         // CSR-ordered (tail | type<<17)
__device__ int   g_headc[NEDGE];         // CSR-ordered head

// ---------------- PTX helpers (sm_100+) ----------------
__device__ __forceinline__ ull fma2(ull a, ull b, ull c) {
    ull d;
    asm("fma.rn.f32x2 %0, %1, %2, %3;" : "=l"(d) : "l"(a), "l"(b), "l"(c));
    return d;
}
__device__ __forceinline__ float2 up2(ull v) {
    float2 f;
    asm("mov.b64 {%0, %1}, %2;" : "=f"(f.x), "=f"(f.y) : "l"(v));
    return f;
}
__device__ __forceinline__ float tanha(float x) {
    float y;
    asm("tanh.approx.f32 %0, %1;" : "=f"(y) : "f"(x));
    return y;
}
__device__ __forceinline__ float neg_inf() { return __int_as_float(0xff800000U); }

// ---------------- CSR build ----------------
__global__ void zero_deg_kernel() {
    int i = blockIdx.x * blockDim.x + threadIdx.x;
    if (i < N_ENT) g_deg[i] = 0;
}

__global__ void count_kernel(const int* __restrict__ head) {
    int e = blockIdx.x * blockDim.x + threadIdx.x;
    if (e < NEDGE) atomicAdd(&g_deg[head[e]], 1);
}

__global__ void scan1_kernel() {
    __shared__ int sh[1024];
    int tid = threadIdx.x;
    int i = blockIdx.x * 1024 + tid;
    int v = (i < N_ENT) ? g_deg[i] : 0;
    sh[tid] = v;
    __syncthreads();
    for (int off = 1; off < 1024; off <<= 1) {
        int t = (tid >= off) ? sh[tid - off] : 0;
        __syncthreads();
        sh[tid] += t;
        __syncthreads();
    }
    if (i < N_ENT) g_rowptr[i] = sh[tid] - v;
    if (tid == 1023) g_bsum[blockIdx.x] = sh[1023];
}

__global__ void scan2_kernel() {
    __shared__ int sh[128];
    int tid = threadIdx.x;
    int v = (tid < SCAN_BLKS) ? g_bsum[tid] : 0;
    sh[tid] = v;
    __syncthreads();
    for (int off = 1; off < 128; off <<= 1) {
        int t = (tid >= off) ? sh[tid - off] : 0;
        __syncthreads();
        sh[tid] += t;
        __syncthreads();
    }
    g_bsum[tid] = sh[tid] - v;
}

__global__ void scan3_kernel() {
    int i = blockIdx.x * blockDim.x + threadIdx.x;
    if (i < N_ENT) {
        int r = g_rowptr[i] + g_bsum[i >> 10];
        g_rowptr[i] = r;
        g_cursor[i] = r;
    }
    if (i == 0) g_rowptr[N_ENT] = NEDGE;
}

__global__ void fill_kernel(const int* __restrict__ head,
                            const int* __restrict__ tail,
                            const int* __restrict__ etype) {
    int e = blockIdx.x * blockDim.x + threadIdx.x;
    if (e < NEDGE) {
        int h = head[e];
        int pos = atomicAdd(&g_cursor[h], 1);
        g_packc[pos] = tail[e] | (etype[e] << 17);   // N_ENT < 2^17, NREL < 2^5
        g_headc[pos] = h;
    }
}

// ---------------- Q = agg @ q_w   (warp per row, packed f32x2 FMA) ----------------
__global__ void gemmq_kernel(const float* agg_in, const float* __restrict__ qw) {
    __shared__ ull qsm[EMB * 32];
    __shared__ ull xs[WARPS][EMB];
    const float* A = agg_in ? agg_in : g_agg;
    const ull* qw64 = (const ull*)qw;
    for (int idx = threadIdx.x; idx < EMB * 32; idx += blockDim.x) qsm[idx] = qw64[idx];
    __syncthreads();
    int w = threadIdx.x >> 5, l = threadIdx.x & 31;
    const float2* A2 = (const float2*)A;
    for (int row = blockIdx.x * WARPS + w; row < N_ENT; row += gridDim.x * WARPS) {
        float2 a2 = A2[row * 32 + l];
        ((float4*)xs[w])[l] = make_float4(a2.x, a2.x, a2.y, a2.y);
        __syncwarp();
        ull acc = 0ull;
        #pragma unroll 8
        for (int i = 0; i < EMB; i++) acc = fma2(qsm[i * 32 + l], xs[w][i], acc);
        float2 r = up2(acc);
        ((float2*)g_Q)[row * 32 + l] = r;
        __syncwarp();
    }
}

// ---------------- pass A: attention logits, edge-centric (no padding) ----------------
// R11 structure (known-good) + index-only prefetch: the next batch's packc/headc
// (16 int regs) are loaded while the current batch's GEMM runs, cutting the
// per-batch serial chain from two L2 trips (index -> gather) to one.
// f32x2 lanes carry (even-k, odd-k) partials; xs undup'd so one broadcast LDS.128
// feeds 4 fma2; lane-major K tables give conflict-free kv LDS.128 shared by 8 edges.
__global__ void __launch_bounds__(256, 2) attA_kernel(const float* agg_in,
                                                      const float* __restrict__ edge_emb,
                                                      const float* __restrict__ kw) {
    __shared__ float4 ksmA[16 * 32];        // 8KB : [kb][l] = kw[4kb..4kb+3][2l]
    __shared__ float4 ksmB[16 * 32];        // 8KB : [kb][l] = kw[4kb..4kb+3][2l+1]
    __shared__ ull relsm[NREL * 32];        // 8KB
    __shared__ __align__(16) float xs[WARPS][EPA][EMB];  // 16KB (undup'd)
    const float* A = agg_in ? agg_in : g_agg;
    const ull* re64 = (const ull*)edge_emb;

    for (int idx = threadIdx.x; idx < 16 * 32; idx += blockDim.x) {
        int kb = idx >> 5, lc = idx & 31;
        int k0 = kb * 4;
        int d0 = lc * 2, d1 = lc * 2 + 1;
        ksmA[idx] = make_float4(kw[(k0 + 0) * EMB + d0], kw[(k0 + 1) * EMB + d0],
                                kw[(k0 + 2) * EMB + d0], kw[(k0 + 3) * EMB + d0]);
        ksmB[idx] = make_float4(kw[(k0 + 0) * EMB + d1], kw[(k0 + 1) * EMB + d1],
                                kw[(k0 + 2) * EMB + d1], kw[(k0 + 3) * EMB + d1]);
    }
    for (int idx = threadIdx.x; idx < NREL * 32; idx += blockDim.x) relsm[idx] = re64[idx];
    __syncthreads();

    int w = threadIdx.x >> 5, l = threadIdx.x & 31;
    const float2* A2 = (const float2*)A;
    const float2* Q2 = (const float2*)g_Q;

    const int stride = gridDim.x * WARPS * EPA;
    int base = (blockIdx.x * WARPS + w) * EPA;

    int pw[EPA], hh[EPA];                        // indices only (16 regs)
    if (base < NEDGE) {
        #pragma unroll
        for (int e = 0; e < EPA; e++) {
            pw[e] = g_packc[base + e];
            hh[e] = g_headc[base + e];
        }
    }

    while (base < NEDGE) {
        // gathers for THIS batch: addresses known immediately from prefetched indices;
        // 8-wide independent loads (MLP) then consumed. q gathers resolve during GEMM.
        float2 q[EPA];
        #pragma unroll
        for (int e = 0; e < EPA; e++) {
            float2 ag = A2[(pw[e] & 0x1FFFF) * 32 + l];
            float2 rr = up2(relsm[(pw[e] >> 17) * 32 + l]);
            q[e] = Q2[hh[e] * 32 + l];
            ((float2*)xs[w][e])[l] = make_float2(rr.x * ag.x, rr.y * ag.y);
        }

        // prefetch NEXT batch's indices (overlaps the GEMM below)
        int nb = base + stride;
        if (nb < NEDGE) {
            #pragma unroll
            for (int e = 0; e < EPA; e++) {
                pw[e] = g_packc[nb + e];
                hh[e] = g_headc[nb + e];
            }
        }
        __syncwarp();

        ull acc0[EPA], acc1[EPA];
        #pragma unroll
        for (int e = 0; e < EPA; e++) { acc0[e] = 0ull; acc1[e] = 0ull; }
        #pragma unroll
        for (int kb = 0; kb < 16; kb++) {
            ulonglong2 ka  = *(const ulonglong2*)&ksmA[kb * 32 + l];  // shared by 8 edges
            ulonglong2 kbv = *(const ulonglong2*)&ksmB[kb * 32 + l];
            #pragma unroll
            for (int e = 0; e < EPA; e++) {
                ulonglong2 xv = *(const ulonglong2*)&xs[w][e][kb * 4]; // broadcast, 4 k's
                acc0[e] = fma2(xv.x, ka.x,  acc0[e]);
                acc0[e] = fma2(xv.y, ka.y,  acc0[e]);
                acc1[e] = fma2(xv.x, kbv.x, acc1[e]);
                acc1[e] = fma2(xv.y, kbv.y, acc1[e]);
            }
        }

        #pragma unroll
        for (int e = 0; e < EPA; e++) {
            float2 s0 = up2(acc0[e]);   // (even-k, odd-k) partial sums for dim 2l
            float2 s1 = up2(acc1[e]);   // same for dim 2l+1
            float d = tanha(s0.x + s0.y) * q[e].x + tanha(s1.x + s1.y) * q[e].y;
            #pragma unroll
            for (int o = 16; o; o >>= 1) d += __shfl_xor_sync(0xffffffffu, d, o);
            if (l == e) g_att[base + e] = d;
        }
        __syncwarp();                   // GEMM reads done before next iter's xs stores
        base = nb;
    }
}

// ---------------- pass B: softmax + weighted scatter-mean + l2norm + kg ----------------
__global__ void passB_kernel(const float* agg_in,
                             const float* __restrict__ edge_emb,
                             const float* __restrict__ ent,
                             float* kg, int accumulate, int write_agg) {
    __shared__ ull relsm[NREL * 32];
    const float* A = agg_in ? agg_in : g_agg;
    const ull* re64 = (const ull*)edge_emb;
    for (int idx = threadIdx.x; idx < NREL * 32; idx += blockDim.x) relsm[idx] = re64[idx];
    __syncthreads();

    int w = threadIdx.x >> 5, l = threadIdx.x & 31;
    const float2* A2 = (const float2*)A;
    const float2* E2 = (const float2*)ent;
    float2* KG2 = (float2*)kg;

    for (int h = blockIdx.x * WARPS + w; h < N_ENT; h += gridDim.x * WARPS) {
        int rs = g_rowptr[h], re = g_rowptr[h + 1];
        int deg = re - rs;

        // sweep 1: exact max of logits (uniform broadcast loads, L1/L2 resident)
        float m = neg_inf();
        int j = rs;
        for (; j + 4 <= re; j += 4) {
            float v0 = g_att[j], v1 = g_att[j + 1], v2 = g_att[j + 2], v3 = g_att[j + 3];
            m = fmaxf(m, fmaxf(fmaxf(v0, v1), fmaxf(v2, v3)));
        }
        for (; j < re; j++) m = fmaxf(m, g_att[j]);

        // sweep 2: exp + gather + accumulate
        float ssum = 0.f, a0 = 0.f, a1 = 0.f;
        int pwv[EPB]; float avv[EPB]; float2 nag[EPB];
        int j0 = rs;
        if (j0 < re) {
            int nv = re - j0; if (nv > EPB) nv = EPB;
            #pragma unroll
            for (int e = 0; e < EPB; e++) {
                pwv[e] = (e < nv) ? g_packc[j0 + e] : 0;
                avv[e] = (e < nv) ? g_att[j0 + e] : neg_inf();
                nag[e] = (e < nv) ? A2[(pwv[e] & 0x1FFFF) * 32 + l] : make_float2(0.f, 0.f);
            }
        }
        while (j0 < re) {
            float x0[EPB], x1[EPB], p[EPB];
            #pragma unroll
            for (int e = 0; e < EPB; e++) {
                float2 rr = up2(relsm[(pwv[e] >> 17) * 32 + l]);
                x0[e] = rr.x * nag[e].x;
                x1[e] = rr.y * nag[e].y;
                p[e]  = __expf(avv[e] - m);          // -inf slots -> 0
            }
            int j1 = j0 + EPB;
            if (j1 < re) {                           // prefetch next batch
                int nv2 = re - j1; if (nv2 > EPB) nv2 = EPB;
                #pragma unroll
                for (int e = 0; e < EPB; e++) {
                    pwv[e] = (e < nv2) ? g_packc[j1 + e] : 0;
                    avv[e] = (e < nv2) ? g_att[j1 + e] : neg_inf();
                    nag[e] = (e < nv2) ? A2[(pwv[e] & 0x1FFFF) * 32 + l] : make_float2(0.f, 0.f);
                }
            }
            #pragma unroll
            for (int e = 0; e < EPB; e++) {
                ssum += p[e];
                a0   += p[e] * x0[e];
                a1   += p[e] * x1[e];
            }
            j0 = j1;
        }

        float v0 = 0.f, v1 = 0.f;
        if (deg > 0) {
            float inv = 1.f / (ssum * (float)deg);   // softmax denom * scatter_mean count
            v0 = a0 * inv; v1 = a1 * inv;
        }
        float sq = v0 * v0 + v1 * v1;
        #pragma unroll
        for (int o = 16; o; o >>= 1) sq += __shfl_xor_sync(0xffffffffu, sq, o);
        float rn = 1.f / fmaxf(sqrtf(sq), 1e-12f);
        v0 *= rn; v1 *= rn;

        if (write_agg) ((float2*)g_agg)[h * 32 + l] = make_float2(v0, v1);
        float2 e2 = E2[h * 32 + l];
        float2 o2;
        if (accumulate) {
            float2 kold = KG2[h * 32 + l];
            o2 = make_float2(kold.x + v0 + e2.x, kold.y + v1 + e2.y);
        } else {
            o2 = make_float2(v0 + e2.x, v1 + e2.y);
        }
        KG2[h * 32 + l] = o2;
    }
}

// ---------------- launch ----------------
extern "C" void kernel_launch(void* const* d_in, const int* in_sizes, int n_in,
                              void* d_out, int out_size) {
    const float* ent      = (const float*)d_in[0];
    const float* edge_emb = (const float*)d_in[1];
    const float* qw       = (const float*)d_in[2];
    const float* kw       = (const float*)d_in[3];
    const int*   eidx     = (const int*)d_in[4];
    const int*   etype    = (const int*)d_in[5];
    const int* head = eidx;
    const int* tail = eidx + NEDGE;
    float* kg = (float*)d_out;

    // CSR build (head identical across hops -> build once per launch)
    zero_deg_kernel<<<(N_ENT + 255) / 256, 256>>>();
    count_kernel<<<(NEDGE + 255) / 256, 256>>>(head);
    scan1_kernel<<<SCAN_BLKS, 1024>>>();
    scan2_kernel<<<1, 128>>>();
    scan3_kernel<<<(N_ENT + 255) / 256, 256>>>();
    fill_kernel<<<(NEDGE + 255) / 256, 256>>>(head, tail, etype);

    // hop 1: agg = entity_emb
    gemmq_kernel<<<2048, 256>>>(ent, qw);
    attA_kernel<<<3125, 256>>>(ent, edge_emb, kw);
    passB_kernel<<<3125, 256>>>(ent, edge_emb, ent, kg, /*accumulate=*/0, /*write_agg=*/1);

    // hop 2: agg = g_agg
    gemmq_kernel<<<2048, 256>>>(nullptr, qw);
    attA_kernel<<<3125, 256>>>(nullptr, edge_emb, kw);
    passB_kernel<<<3125, 256>>>(nullptr, edge_emb, ent, kg, /*accumulate=*/1, /*write_agg=*/0);
}